// round 5
// baseline (speedup 1.0000x reference)
#include <cuda_runtime.h>
#include <cuda_fp16.h>
#include <cstdint>

#define NN 4096
#define FF 256

// ---------------- scratch (device globals; no allocations) ----------------
__device__ float g_h[NN * FF];                    // 4 MB fp32 h
__device__ float g_e1[NN];
__device__ float g_e2[NN];
__device__ float g_tw[NN];                        // e1[r] * t[r]
__device__ float g_wnode[NN];
__device__ unsigned int g_hmax_bits;              // max |h| (float bits, >=0)
__device__ float g_S;                             // fp16 scale
__device__ float g_invS;
__device__ uint32_t g_adjbits[(size_t)NN * 128];  // 2 MB  adj bitmask [4096][128 words]
__device__ __half g_gh[(size_t)NN * FF];          // 2 MB  S * wnode_j * h[j][n], fp16
__device__ float g_part[4 * (size_t)NN * FF];     // 16 MB split-K partials

// ---------------- kernel 1: h = x @ W^T + b (fp32 SIMT tiled) ----------------
__global__ __launch_bounds__(256) void gemm_h_kernel(const float* __restrict__ x,
                                                     const float* __restrict__ W,
                                                     const float* __restrict__ b) {
    __shared__ __align__(16) float xs[16][68];
    __shared__ __align__(16) float ws[16][68];
    const int t = threadIdx.x;
    const int tx = t & 15, ty = t >> 4;
    const int bm = blockIdx.x, bn = blockIdx.y;
    const int r = t >> 2, seg = t & 3;

    float acc[4][4];
#pragma unroll
    for (int i = 0; i < 4; i++)
#pragma unroll
        for (int j = 0; j < 4; j++) acc[i][j] = 0.f;

    for (int kt = 0; kt < 16; ++kt) {
        float4 xv = *(const float4*)(x + (size_t)(bm * 64 + r) * 256 + kt * 16 + seg * 4);
        float4 wv = *(const float4*)(W + (size_t)(bn * 64 + r) * 256 + kt * 16 + seg * 4);
        xs[seg * 4 + 0][r] = xv.x; xs[seg * 4 + 1][r] = xv.y;
        xs[seg * 4 + 2][r] = xv.z; xs[seg * 4 + 3][r] = xv.w;
        ws[seg * 4 + 0][r] = wv.x; ws[seg * 4 + 1][r] = wv.y;
        ws[seg * 4 + 2][r] = wv.z; ws[seg * 4 + 3][r] = wv.w;
        __syncthreads();
#pragma unroll
        for (int k = 0; k < 16; ++k) {
            float4 xa = *(const float4*)&xs[k][ty * 4];
            float4 wb = *(const float4*)&ws[k][tx * 4];
            float xr[4] = {xa.x, xa.y, xa.z, xa.w};
            float wr[4] = {wb.x, wb.y, wb.z, wb.w};
#pragma unroll
            for (int i = 0; i < 4; i++)
#pragma unroll
                for (int j = 0; j < 4; j++) acc[i][j] += xr[i] * wr[j];
        }
        __syncthreads();
    }
#pragma unroll
    for (int i = 0; i < 4; i++) {
        int row = bm * 64 + ty * 4 + i;
#pragma unroll
        for (int j = 0; j < 4; j++) {
            int col = bn * 64 + tx * 4 + j;
            g_h[(size_t)row * 256 + col] = acc[i][j] + b[col];
        }
    }
}

// ---------------- kernel 2: e1/e2 = exp(h.w1/2); also global max|h| ----------------
__global__ __launch_bounds__(256) void a12_kernel(const float* __restrict__ att_w) {
    __shared__ float aw[512];
    const int t = threadIdx.x;
    aw[t] = att_w[t];
    aw[t + 256] = att_w[t + 256];
    __syncthreads();
    const int warp = t >> 5, lane = t & 31;
    const int row = blockIdx.x * 8 + warp;
    const float* hr = g_h + (size_t)row * 256;
    float s1 = 0.f, s2 = 0.f, hm = 0.f;
#pragma unroll
    for (int q = 0; q < 2; q++) {
        int f = lane * 8 + q * 4;
        float4 hv = *(const float4*)(hr + f);
        float4 w1 = *(const float4*)(aw + f);
        float4 w2 = *(const float4*)(aw + 256 + f);
        s1 += hv.x * w1.x + hv.y * w1.y + hv.z * w1.z + hv.w * w1.w;
        s2 += hv.x * w2.x + hv.y * w2.y + hv.z * w2.z + hv.w * w2.w;
        hm = fmaxf(hm, fmaxf(fmaxf(fabsf(hv.x), fabsf(hv.y)),
                             fmaxf(fabsf(hv.z), fabsf(hv.w))));
    }
#pragma unroll
    for (int d = 16; d; d >>= 1) {
        s1 += __shfl_down_sync(0xffffffffu, s1, d);
        s2 += __shfl_down_sync(0xffffffffu, s2, d);
        hm = fmaxf(hm, __shfl_down_sync(0xffffffffu, hm, d));
    }
    if (lane == 0) {
        g_e1[row] = expf(s1);
        g_e2[row] = expf(s2);
        atomicMax(&g_hmax_bits, __float_as_uint(hm));  // |h|>=0: uint order == float order
    }
}

// ---------------- kernel 3: t[i] = sum_j adj[i,j]*e2[j]; adj -> bitmask ----------------
__global__ __launch_bounds__(256) void row_stats_kernel(const int* __restrict__ adj) {
    const int r = blockIdx.x, t = threadIdx.x;
    const int4* arow = (const int4*)(adj + (size_t)r * 4096) + t * 4;
    float s = 0.f;
    uint32_t mask = 0;
#pragma unroll
    for (int q = 0; q < 4; q++) {
        int4 a = arow[q];
        int j = t * 16 + q * 4;
        float4 ev = *(const float4*)(g_e2 + j);
        int f0 = (a.x == 1), f1 = (a.y == 1), f2 = (a.z == 1), f3 = (a.w == 1);
        s += (f0 ? ev.x : 0.f) + (f1 ? ev.y : 0.f) + (f2 ? ev.z : 0.f) + (f3 ? ev.w : 0.f);
        mask |= ((uint32_t)f0 << (q * 4)) | ((uint32_t)f1 << (q * 4 + 1)) |
                ((uint32_t)f2 << (q * 4 + 2)) | ((uint32_t)f3 << (q * 4 + 3));
    }
    __shared__ uint32_t masks[256];
    masks[t] = mask;
    const int lane = t & 31, warp = t >> 5;
#pragma unroll
    for (int d = 16; d; d >>= 1) s += __shfl_down_sync(0xffffffffu, s, d);
    __shared__ float wsum[8];
    if (lane == 0) wsum[warp] = s;
    __syncthreads();
    if (t < 128) {
        g_adjbits[(size_t)r * 128 + t] = masks[2 * t] | (masks[2 * t + 1] << 16);
    }
    if (t == 0) {
        float tot = 0.f;
#pragma unroll
        for (int w2 = 0; w2 < 8; w2++) tot += wsum[w2];
        g_tw[r] = g_e1[r] * tot;
    }
}

// ---------------- kernel 4: denom + w_node scan (bitmask) + scale S ----------------
__global__ __launch_bounds__(1024) void wnode_kernel() {
    __shared__ float redf[32];
    __shared__ int wscan[4];
    __shared__ int s_base;
    __shared__ float s_inv;
    const int t = threadIdx.x, lane = t & 31, warp = t >> 5;

    // denom = sum_r g_tw[r]
    float sd = 0.f;
#pragma unroll
    for (int i = 0; i < 4; i++) sd += g_tw[t + i * 1024];
#pragma unroll
    for (int d = 16; d; d >>= 1) sd += __shfl_down_sync(0xffffffffu, sd, d);
    if (lane == 0) redf[warp] = sd;
    __syncthreads();
    if (warp == 0) {
        float v = redf[lane];
#pragma unroll
        for (int d = 16; d; d >>= 1) v += __shfl_down_sync(0xffffffffu, v, d);
        if (lane == 0) {
            s_inv = 1.f / v;
            s_base = 0;
        }
    }
    __syncthreads();
    const float inv = s_inv;
    float lmax = 0.f;

    for (int r = 0; r < NN; ++r) {
        int base = s_base;
        if (base >= NN) break;
        uint32_t wbits = 0;
        int pc = 0;
        if (t < 128) {
            wbits = g_adjbits[(size_t)r * 128 + t];
            pc = __popc(wbits);
        }
        int incl = pc;
#pragma unroll
        for (int d = 1; d < 32; d <<= 1) {
            int v = __shfl_up_sync(0xffffffffu, incl, d);
            if (lane >= d) incl += v;
        }
        if (warp < 4 && lane == 31) wscan[warp] = incl;
        __syncthreads();
        if (t < 128) {
            int wbase = 0;
#pragma unroll
            for (int u = 0; u < 4; u++) wbase += (u < warp) ? wscan[u] : 0;
            int pos = base + wbase + incl - pc;
            float e1r = g_e1[r];
            uint32_t bb = wbits;
            while (bb) {
                int bit = __ffs(bb) - 1;
                bb &= bb - 1;
                if (pos < NN) {
                    float v = e1r * g_e2[t * 32 + bit] * inv;
                    g_wnode[pos] = v;
                    lmax = fmaxf(lmax, v);
                }
                pos++;
            }
        }
        __syncthreads();
        if (t == 0) s_base = base + wscan[0] + wscan[1] + wscan[2] + wscan[3];
        __syncthreads();
    }

    // reduce lmax, compute S
#pragma unroll
    for (int d = 16; d; d >>= 1) lmax = fmaxf(lmax, __shfl_down_sync(0xffffffffu, lmax, d));
    if (lane == 0) redf[warp] = lmax;
    __syncthreads();
    if (warp == 0) {
        float v = redf[lane];
#pragma unroll
        for (int d = 16; d; d >>= 1) v = fmaxf(v, __shfl_down_sync(0xffffffffu, v, d));
        if (lane == 0) {
            float hmax = __uint_as_float(g_hmax_bits);
            float denom2 = v * hmax;
            g_S = 4096.f / denom2;
            g_invS = denom2 * (1.f / 4096.f);
        }
    }
}

// ---------------- kernel 5: g = S * wnode .* h -> fp16 [4096][256] ----------------
__global__ __launch_bounds__(128) void gscale_kernel() {
    const int j = blockIdx.x, t = threadIdx.x;
    const float ws = g_wnode[j] * g_S;
    float2 hv = *(const float2*)(g_h + (size_t)j * 256 + t * 2);
    __half2 o;
    o.x = __float2half(ws * hv.x);
    o.y = __float2half(ws * hv.y);
    ((__half2*)g_gh)[j * 128 + t] = o;
}

// ---------------- mma / ldmatrix / cp.async helpers ----------------
__device__ __forceinline__ void mma_f16(float& c0, float& c1, float& c2, float& c3,
                                        uint32_t a0, uint32_t a1, uint32_t a2, uint32_t a3,
                                        uint32_t b0, uint32_t b1) {
    asm volatile(
        "mma.sync.aligned.m16n8k16.row.col.f32.f16.f16.f32 "
        "{%0,%1,%2,%3}, {%4,%5,%6,%7}, {%8,%9}, {%0,%1,%2,%3};\n"
        : "+f"(c0), "+f"(c1), "+f"(c2), "+f"(c3)
        : "r"(a0), "r"(a1), "r"(a2), "r"(a3), "r"(b0), "r"(b1));
}
__device__ __forceinline__ void ldsm4t(uint32_t& r0, uint32_t& r1, uint32_t& r2, uint32_t& r3,
                                       uint32_t addr) {
    asm volatile("ldmatrix.sync.aligned.m8n8.x4.trans.shared.b16 {%0,%1,%2,%3}, [%4];"
                 : "=r"(r0), "=r"(r1), "=r"(r2), "=r"(r3)
                 : "r"(addr));
}
__device__ __forceinline__ void cp16(uint32_t dst, const void* src) {
    asm volatile("cp.async.cg.shared.global [%0], [%1], 16;" :: "r"(dst), "l"(src));
}
#define CP_COMMIT() asm volatile("cp.async.commit_group;" ::: "memory")
#define CP_WAIT2() asm volatile("cp.async.wait_group 2;" ::: "memory")

// ---------------- kernel 6: HMMA GEMM: part[split] = expand(adjbits) @ g ----------------
// BM=128, BN=256(full), BK=64, splitK=4, 512 threads (16 warps: 4M x 4N).
// A comes from the bitmask held in smem; fragments built in registers.
// B: 3-stage cp.async pipeline. grid (32 m-tiles, 4 k-splits).
#define BITS_STRIDE 36                         // words per bits row (padded, 16B aligned)
#define BITS_BYTES (128 * BITS_STRIDE * 4)     // 18432
#define B_STRIDE 264                           // halves per B smem row (64 rows)
#define B_STAGE_HALVES (64 * B_STRIDE)         // 16896
#define SMEM_DYN (BITS_BYTES + 3 * B_STAGE_HALVES * 2)

__global__ __launch_bounds__(512, 1) void gemm_out_hmma_kernel() {
    extern __shared__ __align__(16) char smem[];
    uint32_t* bitsS = (uint32_t*)smem;
    __half* Bs[3];
#pragma unroll
    for (int s = 0; s < 3; s++) Bs[s] = (__half*)(smem + BITS_BYTES) + s * B_STAGE_HALVES;

    const int t = threadIdx.x;
    const int warp = t >> 5, lane = t & 31;
    const int wm = warp & 3, wn = warp >> 2;
    const int m0 = blockIdx.x * 128;
    const int kw0 = blockIdx.y * 32;  // first bits-word of this CTA's K range

    float c[2][8][4];
#pragma unroll
    for (int i = 0; i < 2; i++)
#pragma unroll
        for (int j = 0; j < 8; j++)
#pragma unroll
            for (int q = 0; q < 4; q++) c[i][j][q] = 0.f;

    // ---- load whole bits tile (128 rows x 32 words) once ----
    {
        uint32_t bbase = (uint32_t)__cvta_generic_to_shared(bitsS);
#pragma unroll
        for (int i = 0; i < 2; i++) {
            int task = t + i * 512;           // 1024 tasks of 16B
            int row = task >> 3, seg = task & 7;
            cp16(bbase + (row * BITS_STRIDE + seg * 4) * 4,
                 g_adjbits + (size_t)(m0 + row) * 128 + kw0 + seg * 4);
        }
        CP_COMMIT();
    }

    // ---- B stage loader ----
    auto load_B = [&](int slot, int kt) {
        const int k0 = blockIdx.y * 1024 + kt * 64;
        uint32_t bbase = (uint32_t)__cvta_generic_to_shared(Bs[slot]);
#pragma unroll
        for (int i = 0; i < 4; i++) {  // 2048 chunks of 16B
            int q = t + i * 512;
            int row = q >> 5, seg = q & 31;
            cp16(bbase + (row * B_STRIDE + seg * 8) * 2,
                 g_gh + (size_t)(k0 + row) * 256 + seg * 8);
        }
        CP_COMMIT();
    };

    load_B(0, 0);
    load_B(1, 1);
    load_B(2, 2);

    const int s_lo = (lane & 3) * 2;

    for (int kt = 0; kt < 16; ++kt) {
        const int slot = kt % 3;
        CP_WAIT2();
        __syncthreads();
        const __half* b_s = Bs[slot];

        // hoist bits words for this kt: [mi][rowhalf][khalf]
        uint32_t wa[2][2][2];
#pragma unroll
        for (int mi = 0; mi < 2; ++mi) {
            int ra = wm * 32 + mi * 16 + (lane >> 2);
            wa[mi][0][0] = bitsS[ra * BITS_STRIDE + kt * 2];
            wa[mi][0][1] = bitsS[ra * BITS_STRIDE + kt * 2 + 1];
            wa[mi][1][0] = bitsS[(ra + 8) * BITS_STRIDE + kt * 2];
            wa[mi][1][1] = bitsS[(ra + 8) * BITS_STRIDE + kt * 2 + 1];
        }

#pragma unroll
        for (int ks = 0; ks < 4; ++ks) {
            const int kh = ks >> 1;
            const int s = ((ks & 1) << 4) + s_lo;
            uint32_t a[2][4];
#pragma unroll
            for (int mi = 0; mi < 2; ++mi) {
                uint32_t w0 = wa[mi][0][kh], w1 = wa[mi][1][kh];
                a[mi][0] = ((w0 >> s) & 1u) * 0x3C00u | ((w0 >> (s + 1)) & 1u) * 0x3C000000u;
                a[mi][1] = ((w1 >> s) & 1u) * 0x3C00u | ((w1 >> (s + 1)) & 1u) * 0x3C000000u;
                a[mi][2] = ((w0 >> (s + 8)) & 1u) * 0x3C00u | ((w0 >> (s + 9)) & 1u) * 0x3C000000u;
                a[mi][3] = ((w1 >> (s + 8)) & 1u) * 0x3C00u | ((w1 >> (s + 9)) & 1u) * 0x3C000000u;
            }
#pragma unroll
            for (int ng = 0; ng < 4; ++ng) {
                int krow = ks * 16 + (lane & 15);
                int col = wn * 64 + ng * 16 + ((lane >> 4) << 3);
                uint32_t b0, b1, b2, b3;
                uint32_t addr =
                    (uint32_t)__cvta_generic_to_shared(b_s + krow * B_STRIDE + col);
                ldsm4t(b0, b1, b2, b3, addr);
#pragma unroll
                for (int mi = 0; mi < 2; ++mi) {
                    mma_f16(c[mi][ng * 2][0], c[mi][ng * 2][1],
                            c[mi][ng * 2][2], c[mi][ng * 2][3],
                            a[mi][0], a[mi][1], a[mi][2], a[mi][3], b0, b1);
                    mma_f16(c[mi][ng * 2 + 1][0], c[mi][ng * 2 + 1][1],
                            c[mi][ng * 2 + 1][2], c[mi][ng * 2 + 1][3],
                            a[mi][0], a[mi][1], a[mi][2], a[mi][3], b2, b3);
                }
            }
        }
        __syncthreads();
        if (kt + 3 < 16) load_B(slot, kt + 3);
        else CP_COMMIT();  // empty group keeps wait_group count uniform
    }

    // epilogue: fp32 partials
    float* dst = g_part + (size_t)blockIdx.y * NN * FF;
    const int g = lane >> 2, tg = lane & 3;
#pragma unroll
    for (int mi = 0; mi < 2; ++mi) {
        int row0 = m0 + wm * 32 + mi * 16 + g;
#pragma unroll
        for (int nb = 0; nb < 8; ++nb) {
            int col = wn * 64 + nb * 8 + tg * 2;
            float2 v0 = {c[mi][nb][0], c[mi][nb][1]};
            float2 v1 = {c[mi][nb][2], c[mi][nb][3]};
            *(float2*)(dst + (size_t)row0 * 256 + col) = v0;
            *(float2*)(dst + (size_t)(row0 + 8) * 256 + col) = v1;
        }
    }
}

// ---------------- kernel 7: out = relu(sum partials) * invS ----------------
__global__ __launch_bounds__(256) void relu_sum_kernel(float* __restrict__ out) {
    const float invS = g_invS;
    const size_t idx = (size_t)(blockIdx.x * 256 + threadIdx.x) * 4;
    float4 a = *(const float4*)(g_part + idx);
    float4 b = *(const float4*)(g_part + (size_t)NN * FF + idx);
    float4 c = *(const float4*)(g_part + 2 * (size_t)NN * FF + idx);
    float4 d = *(const float4*)(g_part + 3 * (size_t)NN * FF + idx);
    float4 v;
    v.x = fmaxf(a.x + b.x + c.x + d.x, 0.f) * invS;
    v.y = fmaxf(a.y + b.y + c.y + d.y, 0.f) * invS;
    v.z = fmaxf(a.z + b.z + c.z + d.z, 0.f) * invS;
    v.w = fmaxf(a.w + b.w + c.w + d.w, 0.f) * invS;
    *(float4*)(out + idx) = v;
}

// ---------------- launch ----------------
extern "C" void kernel_launch(void* const* d_in, const int* in_sizes, int n_in,
                              void* d_out, int out_size) {
    const float* x = (const float*)d_in[0];
    const int* adj = (const int*)d_in[1];
    const float* W = (const float*)d_in[2];
    const float* b = (const float*)d_in[3];
    const float* att_w = (const float*)d_in[4];
    // att_b cancels in the softmax ratio; unused.
    float* out = (float*)d_out;

    static bool attr_set = false;
    if (!attr_set) {
        cudaFuncSetAttribute(gemm_out_hmma_kernel,
                             cudaFuncAttributeMaxDynamicSharedMemorySize, SMEM_DYN);
        attr_set = true;
    }

    gemm_h_kernel<<<dim3(64, 4), 256>>>(x, W, b);
    a12_kernel<<<512, 256>>>(att_w);
    row_stats_kernel<<<4096, 256>>>(adj);
    wnode_kernel<<<1, 1024>>>();
    gscale_kernel<<<4096, 128>>>();
    gemm_out_hmma_kernel<<<dim3(32, 4), 512, SMEM_DYN>>>();
    relu_sum_kernel<<<1024, 256>>>(out);
}